// round 1
// baseline (speedup 1.0000x reference)
#include <cuda_runtime.h>
#include <cuda_bf16.h>
#include <stdint.h>

#define NN 16384
#define KDIM 128
#define MAX_E (1 << 20)
#define SBUF_CAP 2048

typedef unsigned long long u64;

// ---------------- scratch (device globals; no dynamic alloc allowed) --------
__device__ int   g_deg[NN];
__device__ float g_deginv[NN];
__device__ int   g_rowptr[NN + 1];
__device__ int   g_cursor[NN];
__device__ int   g_elist[MAX_E];   // packed linear index: r*16384 + c
__device__ int   g_csrc[MAX_E];    // CSR source lists (by target)
__device__ int   g_ecount;
__device__ float g_agg[NN * KDIM];
__device__ float g_h0[NN * KDIM];
__device__ float g_h1[NN * KDIM];

// ---------------- f32x2 packed helpers --------------------------------------
__device__ __forceinline__ void fma2(u64& d, u64 a, u64 b) {
    asm("fma.rn.f32x2 %0, %1, %2, %0;" : "+l"(d) : "l"(a), "l"(b));
}
__device__ __forceinline__ u64 dup2(float w) {
    u64 r;
    asm("mov.b64 %0, {%1, %1};" : "=l"(r) : "f"(w));
    return r;
}
__device__ __forceinline__ void unpack2(u64 v, float& lo, float& hi) {
    asm("mov.b64 {%0, %1}, %2;" : "=f"(lo), "=f"(hi) : "l"(v));
}

// ---------------- init -------------------------------------------------------
__global__ void init_kernel() {
    int i = blockIdx.x * blockDim.x + threadIdx.x;
    if (i < NN) { g_deg[i] = 0; g_cursor[i] = 0; }
    if (i == 0) g_ecount = 0;
}

// ---------------- pass A: stream adj once, collect edges --------------------
__global__ void scan_adj_kernel(const float4* __restrict__ adj4) {
    __shared__ int s_cnt;
    __shared__ int s_base;
    __shared__ int s_buf[SBUF_CAP];
    if (threadIdx.x == 0) s_cnt = 0;
    __syncthreads();

    const int total4 = (NN / 4) * NN;  // 67,108,864 float4
    const int stride = gridDim.x * blockDim.x;
    const int tid = blockIdx.x * blockDim.x + threadIdx.x;
    const int lane = threadIdx.x & 31;
    const int iters = (total4 + 4 * stride - 1) / (4 * stride);

    for (int it = 0; it < iters; it++) {
        int base = tid + it * 4 * stride;
        float4 v[4];
        int idx[4];
#pragma unroll
        for (int j = 0; j < 4; j++) {
            idx[j] = base + j * stride;
            if (idx[j] < total4) v[j] = __ldcs(&adj4[idx[j]]);
            else                 v[j] = make_float4(0.f, 0.f, 0.f, 0.f);
        }
#pragma unroll
        for (int j = 0; j < 4; j++) {
            int m = ((v[j].x != 0.f) ? 1 : 0) | ((v[j].y != 0.f) ? 2 : 0) |
                    ((v[j].z != 0.f) ? 4 : 0) | ((v[j].w != 0.f) ? 8 : 0);
            if (__any_sync(0xffffffffu, m != 0)) {
                int cnt = __popc(m);
                int pv = cnt;
#pragma unroll
                for (int o = 1; o < 32; o <<= 1) {
                    int u = __shfl_up_sync(0xffffffffu, pv, o);
                    if (lane >= o) pv += u;
                }
                int tot = __shfl_sync(0xffffffffu, pv, 31);
                int wb = 0;
                if (lane == 31) wb = atomicAdd(&s_cnt, tot);
                wb = __shfl_sync(0xffffffffu, wb, 31);
                int off = wb + pv - cnt;
                int e4 = idx[j] * 4;
#pragma unroll
                for (int b = 0; b < 4; b++) {
                    if (m & (1 << b)) {
                        int p = off++;
                        if (p < SBUF_CAP) s_buf[p] = e4 + b;
                        else {
                            int g = atomicAdd(&g_ecount, 1);
                            if (g < MAX_E) g_elist[g] = e4 + b;
                        }
                    }
                }
            }
        }
    }
    __syncthreads();
    int n = s_cnt; if (n > SBUF_CAP) n = SBUF_CAP;
    if (threadIdx.x == 0) s_base = atomicAdd(&g_ecount, n);
    __syncthreads();
    for (int k = threadIdx.x; k < n; k += blockDim.x) g_elist[s_base + k] = s_buf[k];
}

// ---------------- degree count ----------------------------------------------
__global__ void degcount_kernel() {
    int n = g_ecount; if (n > MAX_E) n = MAX_E;
    for (int e = blockIdx.x * blockDim.x + threadIdx.x; e < n;
         e += gridDim.x * blockDim.x) {
        atomicAdd(&g_deg[g_elist[e] & (NN - 1)], 1);
    }
}

// ---------------- exclusive scan (single block, 1024 threads) ---------------
__global__ void prefix_kernel() {
    __shared__ int ss[1024];
    int t = threadIdx.x;
    int base = t * 16;
    int local[16];
    int s = 0;
#pragma unroll
    for (int i = 0; i < 16; i++) {
        int d = g_deg[base + i];
        local[i] = s;
        s += d;
        g_deginv[base + i] = (d > 0) ? (1.0f / (float)d) : 0.0f;
    }
    ss[t] = s;
    __syncthreads();
    for (int o = 1; o < 1024; o <<= 1) {
        int v = (t >= o) ? ss[t - o] : 0;
        __syncthreads();
        ss[t] += v;
        __syncthreads();
    }
    int off = ss[t] - s;  // exclusive
#pragma unroll
    for (int i = 0; i < 16; i++) g_rowptr[base + i] = off + local[i];
    if (t == 1023) g_rowptr[NN] = ss[1023];
}

// ---------------- scatter COO -> CSR ----------------------------------------
__global__ void scatter_kernel() {
    int n = g_ecount; if (n > MAX_E) n = MAX_E;
    for (int e = blockIdx.x * blockDim.x + threadIdx.x; e < n;
         e += gridDim.x * blockDim.x) {
        int idx = g_elist[e];
        int r = idx >> 14;
        int c = idx & (NN - 1);
        int p = g_rowptr[c] + atomicAdd(&g_cursor[c], 1);
        if (p < MAX_E) g_csrc[p] = r;
    }
}

// ---------------- mean aggregation: one warp per target node ----------------
__global__ void aggregate_kernel(const float* __restrict__ xin) {
    int w = (blockIdx.x * blockDim.x + threadIdx.x) >> 5;
    int lane = threadIdx.x & 31;
    if (w >= NN) return;
    int beg = g_rowptr[w];
    int end = g_rowptr[w + 1];
    const float4* x4 = (const float4*)xin;
    float4 acc = make_float4(0.f, 0.f, 0.f, 0.f);
    for (int e = beg; e < end; e++) {
        int s = g_csrc[e];
        float4 v = __ldg(&x4[s * 32 + lane]);
        acc.x += v.x; acc.y += v.y; acc.z += v.z; acc.w += v.w;
    }
    float di = g_deginv[w];
    float4 r = make_float4(acc.x * di, acc.y * di, acc.z * di, acc.w * di);
    ((float4*)g_agg)[w * 32 + lane] = r;
}

// ---------------- fused dual GEMM: out = agg@Wl.T + b + xin@Wr.T ------------
// A1 = agg [NN,128], A2 = xin [NN,128], Wl/Wr [FO,128], b [FO].
// Block tile: 128 nodes x FO outputs, 256 threads, KC=16 chunks.
// f32x2 packed accumulation: pairs along node dim, W duplicated per-register.
template <int FO, bool RELU>
__global__ __launch_bounds__(256, 1) void gemm_kernel(
    const float* __restrict__ A1, const float* __restrict__ A2,
    const float* __restrict__ Wl, const float* __restrict__ b,
    const float* __restrict__ Wr, float* __restrict__ out) {
    constexpr int KC = 16;
    constexpr int FJ = FO / 16;
    __shared__ float sA1[KC][132];
    __shared__ float sA2[KC][132];
    __shared__ float sWl[KC][FO + 4];
    __shared__ float sWr[KC][FO + 4];

    const int tid = threadIdx.x;
    const int tx = tid & 15;        // output lane: f = tx + 16*j
    const int ty = tid >> 4;        // node group: n0 = ty*8
    const int n0 = ty * 8;
    const int nb = blockIdx.x * 128;

    u64 acc[4][FJ];
#pragma unroll
    for (int p = 0; p < 4; p++)
#pragma unroll
        for (int j = 0; j < FJ; j++) acc[p][j] = 0ull;

    const int kq = (tid & 3) * 4;   // k offset within chunk
    const int rr = tid >> 2;        // 0..63

    for (int kc0 = 0; kc0 < KDIM; kc0 += KC) {
#pragma unroll
        for (int h = 0; h < 2; h++) {
            int n = rr + h * 64;
            float4 va = *(const float4*)&A1[(nb + n) * KDIM + kc0 + kq];
            sA1[kq + 0][n] = va.x; sA1[kq + 1][n] = va.y;
            sA1[kq + 2][n] = va.z; sA1[kq + 3][n] = va.w;
            float4 vb = *(const float4*)&A2[(nb + n) * KDIM + kc0 + kq];
            sA2[kq + 0][n] = vb.x; sA2[kq + 1][n] = vb.y;
            sA2[kq + 2][n] = vb.z; sA2[kq + 3][n] = vb.w;
        }
        for (int f = rr; f < FO; f += 64) {
            float4 wv = *(const float4*)&Wl[f * KDIM + kc0 + kq];
            sWl[kq + 0][f] = wv.x; sWl[kq + 1][f] = wv.y;
            sWl[kq + 2][f] = wv.z; sWl[kq + 3][f] = wv.w;
            float4 wu = *(const float4*)&Wr[f * KDIM + kc0 + kq];
            sWr[kq + 0][f] = wu.x; sWr[kq + 1][f] = wu.y;
            sWr[kq + 2][f] = wu.z; sWr[kq + 3][f] = wu.w;
        }
        __syncthreads();

#pragma unroll 4
        for (int kk = 0; kk < KC; kk++) {
            const u64* pa1 = reinterpret_cast<const u64*>(&sA1[kk][n0]);
            const u64* pa2 = reinterpret_cast<const u64*>(&sA2[kk][n0]);
            u64 a1[4], a2[4];
#pragma unroll
            for (int p = 0; p < 4; p++) { a1[p] = pa1[p]; a2[p] = pa2[p]; }
#pragma unroll
            for (int j = 0; j < FJ; j++) {
                u64 wl2 = dup2(sWl[kk][tx + 16 * j]);
                u64 wr2 = dup2(sWr[kk][tx + 16 * j]);
#pragma unroll
                for (int p = 0; p < 4; p++) {
                    fma2(acc[p][j], a1[p], wl2);
                    fma2(acc[p][j], a2[p], wr2);
                }
            }
        }
        __syncthreads();
    }

#pragma unroll
    for (int j = 0; j < FJ; j++) {
        int f = tx + 16 * j;
        float bv = __ldg(&b[f]);
#pragma unroll
        for (int p = 0; p < 4; p++) {
            float lo, hi;
            unpack2(acc[p][j], lo, hi);
            lo += bv; hi += bv;
            if (RELU) { lo = fmaxf(lo, 0.f); hi = fmaxf(hi, 0.f); }
            int n = nb + n0 + 2 * p;
            out[n * FO + f] = lo;
            out[(n + 1) * FO + f] = hi;
        }
    }
}

// ---------------- launch -----------------------------------------------------
extern "C" void kernel_launch(void* const* d_in, const int* in_sizes, int n_in,
                              void* d_out, int out_size) {
    const float* x   = (const float*)d_in[0];
    const float* adj = (const float*)d_in[1];
    const float* Wl0 = (const float*)d_in[2];
    const float* b0  = (const float*)d_in[3];
    const float* Wr0 = (const float*)d_in[4];
    const float* Wl1 = (const float*)d_in[5];
    const float* b1  = (const float*)d_in[6];
    const float* Wr1 = (const float*)d_in[7];
    const float* Wl2 = (const float*)d_in[8];
    const float* b2  = (const float*)d_in[9];
    const float* Wr2 = (const float*)d_in[10];
    float* out = (float*)d_out;

    float *p_agg, *p_h0, *p_h1;
    cudaGetSymbolAddress((void**)&p_agg, g_agg);
    cudaGetSymbolAddress((void**)&p_h0, g_h0);
    cudaGetSymbolAddress((void**)&p_h1, g_h1);

    init_kernel<<<64, 256>>>();
    scan_adj_kernel<<<1184, 256>>>((const float4*)adj);
    degcount_kernel<<<256, 256>>>();
    prefix_kernel<<<1, 1024>>>();
    scatter_kernel<<<256, 256>>>();

    // layer 0
    aggregate_kernel<<<2048, 256>>>(x);
    gemm_kernel<128, true><<<128, 256>>>(p_agg, x, Wl0, b0, Wr0, p_h0);
    // layer 1
    aggregate_kernel<<<2048, 256>>>(p_h0);
    gemm_kernel<128, true><<<128, 256>>>(p_agg, p_h0, Wl1, b1, Wr1, p_h1);
    // layer 2
    aggregate_kernel<<<2048, 256>>>(p_h1);
    gemm_kernel<64, false><<<128, 256>>>(p_agg, p_h1, Wl2, b2, Wr2, out);
}

// round 2
// speedup vs baseline: 1.1584x; 1.1584x over previous
#include <cuda_runtime.h>
#include <cuda_bf16.h>
#include <stdint.h>

#define NN 16384
#define KDIM 128
#define CAP 96

typedef unsigned long long u64;

// ---------------- scratch (device globals; no dynamic alloc allowed) --------
__device__ int   g_deg[NN];
__device__ int   g_ell[NN * CAP];    // ELL source lists (by target), slot order arbitrary
__device__ float g_agg[NN * KDIM];
__device__ float g_h0[NN * KDIM];
__device__ float g_h1[NN * KDIM];

// ---------------- f32x2 packed helpers --------------------------------------
__device__ __forceinline__ void fma2(u64& d, u64 a, u64 b) {
    asm("fma.rn.f32x2 %0, %1, %2, %0;" : "+l"(d) : "l"(a), "l"(b));
}
__device__ __forceinline__ u64 dup2(float w) {
    u64 r;
    asm("mov.b64 %0, {%1, %1};" : "=l"(r) : "f"(w));
    return r;
}
__device__ __forceinline__ void unpack2(u64 v, float& lo, float& hi) {
    asm("mov.b64 {%0, %1}, %2;" : "=f"(lo), "=f"(hi) : "l"(v));
}

// ---------------- init -------------------------------------------------------
__global__ void init_kernel() {
    int i = blockIdx.x * blockDim.x + threadIdx.x;
    if (i < NN) g_deg[i] = 0;
}

// ---------------- pass A: stream adj once, scatter edges straight to ELL -----
__global__ void scan_adj_kernel(const float4* __restrict__ adj4) {
    const int total4 = (NN / 4) * NN;  // 67,108,864 float4
    const int stride = gridDim.x * blockDim.x;
    const int tid = blockIdx.x * blockDim.x + threadIdx.x;
    const int iters = (total4 + 4 * stride - 1) / (4 * stride);

    for (int it = 0; it < iters; it++) {
        int base = tid + it * 4 * stride;
        float4 v[4];
        int idx[4];
#pragma unroll
        for (int j = 0; j < 4; j++) {
            idx[j] = base + j * stride;
            if (idx[j] < total4) v[j] = __ldcs(&adj4[idx[j]]);
            else                 v[j] = make_float4(0.f, 0.f, 0.f, 0.f);
        }
#pragma unroll
        for (int j = 0; j < 4; j++) {
            int m = ((v[j].x != 0.f) ? 1 : 0) | ((v[j].y != 0.f) ? 2 : 0) |
                    ((v[j].z != 0.f) ? 4 : 0) | ((v[j].w != 0.f) ? 8 : 0);
            if (__any_sync(0xffffffffu, m != 0)) {
                int e4 = idx[j] * 4;
#pragma unroll
                for (int b = 0; b < 4; b++) {
                    if (m & (1 << b)) {
                        int elem = e4 + b;
                        int c = elem & (NN - 1);      // target node
                        int r = elem >> 14;           // source node
                        int slot = atomicAdd(&g_deg[c], 1);
                        if (slot < CAP) g_ell[c * CAP + slot] = r;
                    }
                }
            }
        }
    }
}

// ---------------- mean aggregation: one warp per target node (ELL) ----------
__global__ void aggregate_kernel(const float* __restrict__ xin) {
    int w = (blockIdx.x * blockDim.x + threadIdx.x) >> 5;
    int lane = threadIdx.x & 31;
    if (w >= NN) return;
    int deg = g_deg[w];
    if (deg > CAP) deg = CAP;
    const int* __restrict__ src = &g_ell[w * CAP];
    const float4* __restrict__ x4 = (const float4*)xin;
    float4 acc = make_float4(0.f, 0.f, 0.f, 0.f);
    int e = 0;
    for (; e + 4 <= deg; e += 4) {
        int s0 = __ldg(&src[e + 0]);
        int s1 = __ldg(&src[e + 1]);
        int s2 = __ldg(&src[e + 2]);
        int s3 = __ldg(&src[e + 3]);
        float4 v0 = __ldg(&x4[s0 * 32 + lane]);
        float4 v1 = __ldg(&x4[s1 * 32 + lane]);
        float4 v2 = __ldg(&x4[s2 * 32 + lane]);
        float4 v3 = __ldg(&x4[s3 * 32 + lane]);
        acc.x += v0.x + v1.x + v2.x + v3.x;
        acc.y += v0.y + v1.y + v2.y + v3.y;
        acc.z += v0.z + v1.z + v2.z + v3.z;
        acc.w += v0.w + v1.w + v2.w + v3.w;
    }
    for (; e < deg; e++) {
        int s = __ldg(&src[e]);
        float4 v = __ldg(&x4[s * 32 + lane]);
        acc.x += v.x; acc.y += v.y; acc.z += v.z; acc.w += v.w;
    }
    float di = (deg > 0) ? (1.0f / (float)deg) : 0.0f;
    float4 r = make_float4(acc.x * di, acc.y * di, acc.z * di, acc.w * di);
    ((float4*)g_agg)[w * 32 + lane] = r;
}

// ---------------- fused dual GEMM: out = agg@Wl.T + b + xin@Wr.T ------------
// A1 = agg [NN,128], A2 = xin [NN,128], Wl/Wr [FO,128], b [FO].
// Block tile: 128 nodes x FO outputs, 256 threads, KC=16 chunks.
// f32x2 packed accumulation: pairs along node dim, W duplicated per-register.
template <int FO, bool RELU>
__global__ __launch_bounds__(256, 1) void gemm_kernel(
    const float* __restrict__ A1, const float* __restrict__ A2,
    const float* __restrict__ Wl, const float* __restrict__ b,
    const float* __restrict__ Wr, float* __restrict__ out) {
    constexpr int KC = 16;
    constexpr int FJ = FO / 16;
    __shared__ float sA1[KC][132];
    __shared__ float sA2[KC][132];
    __shared__ float sWl[KC][FO + 4];
    __shared__ float sWr[KC][FO + 4];

    const int tid = threadIdx.x;
    const int tx = tid & 15;        // output lane: f = tx + 16*j
    const int ty = tid >> 4;        // node group: n0 = ty*8
    const int n0 = ty * 8;
    const int nb = blockIdx.x * 128;

    u64 acc[4][FJ];
#pragma unroll
    for (int p = 0; p < 4; p++)
#pragma unroll
        for (int j = 0; j < FJ; j++) acc[p][j] = 0ull;

    const int kq = (tid & 3) * 4;   // k offset within chunk
    const int rr = tid >> 2;        // 0..63

    for (int kc0 = 0; kc0 < KDIM; kc0 += KC) {
#pragma unroll
        for (int h = 0; h < 2; h++) {
            int n = rr + h * 64;
            float4 va = *(const float4*)&A1[(nb + n) * KDIM + kc0 + kq];
            sA1[kq + 0][n] = va.x; sA1[kq + 1][n] = va.y;
            sA1[kq + 2][n] = va.z; sA1[kq + 3][n] = va.w;
            float4 vb = *(const float4*)&A2[(nb + n) * KDIM + kc0 + kq];
            sA2[kq + 0][n] = vb.x; sA2[kq + 1][n] = vb.y;
            sA2[kq + 2][n] = vb.z; sA2[kq + 3][n] = vb.w;
        }
        for (int f = rr; f < FO; f += 64) {
            float4 wv = *(const float4*)&Wl[f * KDIM + kc0 + kq];
            sWl[kq + 0][f] = wv.x; sWl[kq + 1][f] = wv.y;
            sWl[kq + 2][f] = wv.z; sWl[kq + 3][f] = wv.w;
            float4 wu = *(const float4*)&Wr[f * KDIM + kc0 + kq];
            sWr[kq + 0][f] = wu.x; sWr[kq + 1][f] = wu.y;
            sWr[kq + 2][f] = wu.z; sWr[kq + 3][f] = wu.w;
        }
        __syncthreads();

#pragma unroll 4
        for (int kk = 0; kk < KC; kk++) {
            const u64* pa1 = reinterpret_cast<const u64*>(&sA1[kk][n0]);
            const u64* pa2 = reinterpret_cast<const u64*>(&sA2[kk][n0]);
            u64 a1[4], a2[4];
#pragma unroll
            for (int p = 0; p < 4; p++) { a1[p] = pa1[p]; a2[p] = pa2[p]; }
#pragma unroll
            for (int j = 0; j < FJ; j++) {
                u64 wl2 = dup2(sWl[kk][tx + 16 * j]);
                u64 wr2 = dup2(sWr[kk][tx + 16 * j]);
#pragma unroll
                for (int p = 0; p < 4; p++) {
                    fma2(acc[p][j], a1[p], wl2);
                    fma2(acc[p][j], a2[p], wr2);
                }
            }
        }
        __syncthreads();
    }

#pragma unroll
    for (int j = 0; j < FJ; j++) {
        int f = tx + 16 * j;
        float bv = __ldg(&b[f]);
#pragma unroll
        for (int p = 0; p < 4; p++) {
            float lo, hi;
            unpack2(acc[p][j], lo, hi);
            lo += bv; hi += bv;
            if (RELU) { lo = fmaxf(lo, 0.f); hi = fmaxf(hi, 0.f); }
            int n = nb + n0 + 2 * p;
            out[n * FO + f] = lo;
            out[(n + 1) * FO + f] = hi;
        }
    }
}

// ---------------- launch -----------------------------------------------------
extern "C" void kernel_launch(void* const* d_in, const int* in_sizes, int n_in,
                              void* d_out, int out_size) {
    const float* x   = (const float*)d_in[0];
    const float* adj = (const float*)d_in[1];
    const float* Wl0 = (const float*)d_in[2];
    const float* b0  = (const float*)d_in[3];
    const float* Wr0 = (const float*)d_in[4];
    const float* Wl1 = (const float*)d_in[5];
    const float* b1  = (const float*)d_in[6];
    const float* Wr1 = (const float*)d_in[7];
    const float* Wl2 = (const float*)d_in[8];
    const float* b2  = (const float*)d_in[9];
    const float* Wr2 = (const float*)d_in[10];
    float* out = (float*)d_out;

    float *p_agg, *p_h0, *p_h1;
    cudaGetSymbolAddress((void**)&p_agg, g_agg);
    cudaGetSymbolAddress((void**)&p_h0, g_h0);
    cudaGetSymbolAddress((void**)&p_h1, g_h1);

    init_kernel<<<64, 256>>>();
    scan_adj_kernel<<<1184, 256>>>((const float4*)adj);

    // layer 0
    aggregate_kernel<<<2048, 256>>>(x);
    gemm_kernel<128, true><<<128, 256>>>(p_agg, x, Wl0, b0, Wr0, p_h0);
    // layer 1
    aggregate_kernel<<<2048, 256>>>(p_h0);
    gemm_kernel<128, true><<<128, 256>>>(p_agg, p_h0, Wl1, b1, Wr1, p_h1);
    // layer 2
    aggregate_kernel<<<2048, 256>>>(p_h1);
    gemm_kernel<64, false><<<128, 256>>>(p_agg, p_h1, Wl2, b2, Wr2, out);
}